// round 16
// baseline (speedup 1.0000x reference)
#include <cuda_runtime.h>
#include <cuda_fp16.h>
#include <math.h>
#include <stdint.h>

#define BB   4096
#define FF   24
#define VV   1000
#define DD   32
#define FD   768
#define COMB 1536
#define H0N  1024
#define H1N  512
#define RED  8
#define EPSV 1e-5f
#define RCH  32            // row chunks for BN partials (BB/128)

// prep mega-kernel block ranges (all 256-thread blocks)
#define GB_GATHER 4096
#define GB_TRW    (FD * FD / 256)                 // 2304
#define GB_W0     ((COMB / 32) * (H0N / 32))      // 1536
#define GB_W1     ((H0N / 32) * (H1N / 32))       // 512
#define GB_TOTAL  (GB_GATHER + GB_TRW + GB_W0 + GB_W1)

// ---------------- device scratch ----------------
__device__ __align__(16) __half g_E2h[2 * BB * FD];
__device__ __align__(16) __half g_WTn[FD * FD];
__device__ __align__(16) __half g_comb[BB * COMB];
__device__ __align__(16) __half g_h0h[BB * H0N];
__device__ __align__(16) __half g_h0t[BB * H0N];
__device__ __align__(16) __half g_h1h[BB * H1N];
__device__ __align__(16) __half g_w0t[H0N * COMB];
__device__ __align__(16) __half g_w1t[H1N * H0N];
__device__ float g_lin[BB];
__device__ __align__(16) float g_ps[RCH * H0N];   // BN partial sums
__device__ __align__(16) float g_psq[RCH * H0N];  // BN partial sumsq

__device__ __forceinline__ void cp16(unsigned dst, const void* src) {
    asm volatile("cp.async.cg.shared.global [%0], [%1], 16;" :: "r"(dst), "l"(src));
}

// ---------------- mega prep kernel -----------------------------------------
__global__ void __launch_bounds__(256)
prep_kernel(const int* __restrict__ x,
            const float* __restrict__ emb,
            const float* __restrict__ lint,
            const float* __restrict__ sw1,
            const float* __restrict__ sw2,
            const float* __restrict__ W,
            const float* __restrict__ w0,
            const float* __restrict__ w1,
            __half* __restrict__ E2h,
            __half* __restrict__ WTn,
            __half* __restrict__ w0t,
            __half* __restrict__ w1t,
            float* __restrict__ linout) {
    __shared__ union {
        float tile[32][33];
        struct {
            int   xs[FF];
            float es[FD];
            float Zs[FF], hid[RED], As[FF], linp[FF];
        } g;
    } sm;

    int blk = blockIdx.x;
    int t = threadIdx.x;

    if (blk < GB_GATHER) {
        int b = blk;
        if (t < FF) sm.g.xs[t] = x[b * FF + t];
        __syncthreads();

        #pragma unroll
        for (int r = 0; r < 3; r++) {
            int ik = t + r * 256;
            int f = ik >> 5, d = ik & 31;
            sm.g.es[ik] = emb[((long)f * VV + sm.g.xs[f]) * DD + d];
        }
        if (t < FF) sm.g.linp[t] = lint[(long)t * VV + sm.g.xs[t]];
        __syncthreads();

        int w = t >> 5, lane = t & 31;
        #pragma unroll
        for (int ff = 0; ff < 3; ff++) {
            int f = w * 3 + ff;
            float v = sm.g.es[f * 32 + lane];
            #pragma unroll
            for (int o = 16; o > 0; o >>= 1) v += __shfl_xor_sync(0xffffffffu, v, o);
            if (lane == 0) sm.g.Zs[f] = v * (1.f / 32.f);
        }
        __syncthreads();
        if (t < RED) {
            float s = 0.f;
            #pragma unroll
            for (int f = 0; f < FF; f++) s += sm.g.Zs[f] * sw1[t * FF + f];
            sm.g.hid[t] = fmaxf(s, 0.f);
        }
        __syncthreads();
        if (t < FF) {
            float s = 0.f;
            #pragma unroll
            for (int r = 0; r < RED; r++) s += sm.g.hid[r] * sw2[t * RED + r];
            sm.g.As[t] = 1.f / (1.f + expf(-s));
        }
        if (t == 0) {
            float s = 0.f;
            #pragma unroll
            for (int f = 0; f < FF; f++) s += sm.g.linp[f];
            linout[b] = s;
        }
        __syncthreads();

        #pragma unroll
        for (int r = 0; r < 3; r++) {
            int ik = t + r * 256;
            int f = ik >> 5;
            float e = sm.g.es[ik];
            E2h[(long)b * FD + ik] = __float2half_rn(e);
            E2h[(long)(BB + b) * FD + ik] = __float2half_rn(sm.g.As[f] * e);
        }
    } else if (blk < GB_GATHER + GB_TRW) {
        int o = (blk - GB_GATHER) * 256 + t;
        int jl = o % FD, ik = o / FD;
        int i = ik >> 5, k = ik & 31, j = jl >> 5, l = jl & 31;
        float v = (i == j) ? 0.f : W[(((i * FF + j) * DD + k) * DD) + l];
        WTn[o] = __float2half_rn(v);
    } else {
        const float* src;
        __half* dst;
        int K, N, kblk, nblk;
        if (blk < GB_GATHER + GB_TRW + GB_W0) {
            int idx = blk - (GB_GATHER + GB_TRW);
            src = w0; dst = w0t; K = COMB; N = H0N;
            kblk = idx % (COMB / 32); nblk = idx / (COMB / 32);
        } else {
            int idx = blk - (GB_GATHER + GB_TRW + GB_W0);
            src = w1; dst = w1t; K = H0N; N = H1N;
            kblk = idx % (H0N / 32); nblk = idx / (H0N / 32);
        }
        int k0 = kblk * 32, n0 = nblk * 32;
        int tx = t & 31, ty = t >> 5;
        #pragma unroll
        for (int j = 0; j < 4; j++)
            sm.tile[ty + j * 8][tx] = src[(long)(k0 + ty + j * 8) * N + n0 + tx];
        __syncthreads();
        #pragma unroll
        for (int j = 0; j < 4; j++)
            dst[(long)(n0 + ty + j * 8) * K + k0 + tx] =
                __float2half_rn(sm.tile[tx][ty + j * 8]);
    }
}

// ---------------- fp16 GEMM: ldmatrix + m16n8k16 + cp.async 4-stage --------
// BNPART: epilogue also emits per-block column sum/sumsq partials
// (chunk = blockIdx.x) into ps/psq.
template <bool BIAS, bool COMBINE, bool BNPART>
__global__ void __launch_bounds__(128, 2)
hgemm_kernel(const __half* __restrict__ A, const __half* __restrict__ Bt,
             __half* __restrict__ C, int M, int N, int K,
             const float* __restrict__ bias, const __half* __restrict__ E2,
             float* __restrict__ ps, float* __restrict__ psq) {
    __shared__ __align__(16) __half Asm[4][2048];
    __shared__ __align__(16) __half Bsm[4][2048];
    __shared__ float bred_s[4][64], bred_q[4][64];
    int t = threadIdx.x;
    int m0 = blockIdx.x * 128, n0 = blockIdx.y * 128;
    int wid = t >> 5, lane = t & 31;
    int wm = (wid & 1) * 64, wn = (wid >> 1) * 64;
    int r = lane >> 2, quad = lane & 3;

    float acc[4][8][4];
    #pragma unroll
    for (int mi = 0; mi < 4; mi++)
        #pragma unroll
        for (int ni = 0; ni < 8; ni++)
            #pragma unroll
            for (int c = 0; c < 4; c++) acc[mi][ni][c] = 0.f;

    int srow = t >> 1, sc = t & 1;
    const __half* Ap = A + (long)(m0 + srow) * K + sc * 8;
    const __half* Bp = Bt + (long)(n0 + srow) * K + sc * 8;
    int swz = (srow >> 2) & 1;
    unsigned off0 = (unsigned)(srow * 16 + ((sc ^ swz) << 3)) * 2u;
    unsigned off1 = (unsigned)((srow + 64) * 16 + ((sc ^ swz) << 3)) * 2u;

    unsigned abase = (unsigned)__cvta_generic_to_shared(Asm[0]);
    unsigned bbase = (unsigned)__cvta_generic_to_shared(Bsm[0]);

    unsigned aaddr[4], baddr[4];
    #pragma unroll
    for (int mi = 0; mi < 4; mi++) {
        int row = wm + mi * 16 + (lane & 7) + ((lane >> 3) & 1) * 8;
        int kc  = (lane >> 4) & 1;
        aaddr[mi] = abase + (unsigned)(row * 16 + ((kc ^ ((row >> 2) & 1)) << 3)) * 2u;
    }
    #pragma unroll
    for (int np = 0; np < 4; np++) {
        int row = wn + np * 16 + (lane & 7) + ((lane >> 4) & 1) * 8;
        int kc  = (lane >> 3) & 1;
        baddr[np] = bbase + (unsigned)(row * 16 + ((kc ^ ((row >> 2) & 1)) << 3)) * 2u;
    }

    int nt = K >> 4;
    long rstep = 64 * (long)K;

    #define STAGE(i)                                                        \
        do {                                                                \
            if ((i) < nt) {                                                 \
                unsigned bo = (unsigned)((i) & 3) * 4096u;                  \
                const __half* ak = Ap + (i) * 16;                           \
                const __half* bk = Bp + (i) * 16;                           \
                cp16(abase + bo + off0, ak);                                \
                cp16(abase + bo + off1, ak + rstep);                        \
                cp16(bbase + bo + off0, bk);                                \
                cp16(bbase + bo + off1, bk + rstep);                        \
            }                                                               \
            asm volatile("cp.async.commit_group;");                         \
        } while (0)

    STAGE(0); STAGE(1); STAGE(2);

    for (int i = 0; i < nt; i++) {
        asm volatile("cp.async.wait_group 2;");
        __syncthreads();
        unsigned boff = (unsigned)(i & 3) * 4096u;
        unsigned af[4][4], bf[4][4];
        #pragma unroll
        for (int mi = 0; mi < 4; mi++)
            asm volatile("ldmatrix.sync.aligned.m8n8.x4.shared.b16 {%0,%1,%2,%3}, [%4];"
                : "=r"(af[mi][0]), "=r"(af[mi][1]), "=r"(af[mi][2]), "=r"(af[mi][3])
                : "r"(aaddr[mi] + boff));
        #pragma unroll
        for (int np = 0; np < 4; np++)
            asm volatile("ldmatrix.sync.aligned.m8n8.x4.shared.b16 {%0,%1,%2,%3}, [%4];"
                : "=r"(bf[np][0]), "=r"(bf[np][1]), "=r"(bf[np][2]), "=r"(bf[np][3])
                : "r"(baddr[np] + boff));
        #pragma unroll
        for (int mi = 0; mi < 4; mi++)
            #pragma unroll
            for (int ni = 0; ni < 8; ni++) {
                asm volatile(
                    "mma.sync.aligned.m16n8k16.row.col.f32.f16.f16.f32 "
                    "{%0,%1,%2,%3}, {%4,%5,%6,%7}, {%8,%9}, {%0,%1,%2,%3};"
                    : "+f"(acc[mi][ni][0]), "+f"(acc[mi][ni][1]),
                      "+f"(acc[mi][ni][2]), "+f"(acc[mi][ni][3])
                    : "r"(af[mi][0]), "r"(af[mi][1]), "r"(af[mi][2]), "r"(af[mi][3]),
                      "r"(bf[ni >> 1][(ni & 1) * 2]), "r"(bf[ni >> 1][(ni & 1) * 2 + 1]));
            }
        STAGE(i + 3);
    }
    #undef STAGE
    asm volatile("cp.async.wait_group 0;");

    float cs[8][2], cq[8][2];
    if (BNPART) {
        #pragma unroll
        for (int ni = 0; ni < 8; ni++) {
            cs[ni][0] = cs[ni][1] = 0.f;
            cq[ni][0] = cq[ni][1] = 0.f;
        }
    }

    #pragma unroll
    for (int mi = 0; mi < 4; mi++) {
        #pragma unroll
        for (int ni = 0; ni < 8; ni++) {
            int row0 = m0 + wm + mi * 16 + r;
            int row1 = row0 + 8;
            int col  = n0 + wn + ni * 8 + 2 * quad;
            float2 v0 = make_float2(acc[mi][ni][0], acc[mi][ni][1]);
            float2 v1 = make_float2(acc[mi][ni][2], acc[mi][ni][3]);
            if (BIAS) {
                float b0v = bias[col], b1v = bias[col + 1];
                v0.x += b0v; v0.y += b1v;
                v1.x += b0v; v1.y += b1v;
            }
            if (COMBINE) {
                float2 e0 = __half22float2(*(const __half2*)&E2[(long)row0 * FD + col]);
                float2 e1 = __half22float2(*(const __half2*)&E2[(long)row1 * FD + col]);
                v0.x *= e0.x; v0.y *= e0.y;
                v1.x *= e1.x; v1.y *= e1.y;
                long br0 = (row0 < BB) ? row0 : (row0 - BB);
                long br1 = (row1 < BB) ? row1 : (row1 - BB);
                int  c0  = (row0 < BB) ? 0 : FD;
                int  c1  = (row1 < BB) ? 0 : FD;
                *(__half2*)&C[br0 * (long)COMB + c0 + col] = __floats2half2_rn(v0.x, v0.y);
                *(__half2*)&C[br1 * (long)COMB + c1 + col] = __floats2half2_rn(v1.x, v1.y);
            } else {
                __half2 h0 = __floats2half2_rn(v0.x, v0.y);
                __half2 h1 = __floats2half2_rn(v1.x, v1.y);
                *(__half2*)&C[(long)row0 * N + col] = h0;
                *(__half2*)&C[(long)row1 * N + col] = h1;
                if (BNPART) {
                    float2 f0 = __half22float2(h0), f1 = __half22float2(h1);
                    cs[ni][0] += f0.x + f1.x;
                    cs[ni][1] += f0.y + f1.y;
                    cq[ni][0] += f0.x * f0.x + f1.x * f1.x;
                    cq[ni][1] += f0.y * f0.y + f1.y * f1.y;
                }
            }
        }
    }

    if (BNPART) {
        #pragma unroll
        for (int ni = 0; ni < 8; ni++)
            #pragma unroll
            for (int j = 0; j < 2; j++) {
                #pragma unroll
                for (int d = 4; d <= 16; d <<= 1) {
                    cs[ni][j] += __shfl_xor_sync(0xffffffffu, cs[ni][j], d);
                    cq[ni][j] += __shfl_xor_sync(0xffffffffu, cq[ni][j], d);
                }
            }
        if (lane < 4) {
            #pragma unroll
            for (int ni = 0; ni < 8; ni++) {
                bred_s[wid][ni * 8 + 2 * lane + 0] = cs[ni][0];
                bred_s[wid][ni * 8 + 2 * lane + 1] = cs[ni][1];
                bred_q[wid][ni * 8 + 2 * lane + 0] = cq[ni][0];
                bred_q[wid][ni * 8 + 2 * lane + 1] = cq[ni][1];
            }
        }
        __syncthreads();
        if ((wid & 1) == 0) {
            int base = n0 + (wid >> 1) * 64;
            #pragma unroll
            for (int c = lane; c < 64; c += 32) {
                float s = bred_s[wid][c] + bred_s[wid | 1][c];
                float q = bred_q[wid][c] + bred_q[wid | 1][c];
                ps[(long)blockIdx.x * N + base + c]  = s;
                psq[(long)blockIdx.x * N + base + c] = q;
            }
        }
    }
}

// ---------------- fused BN finalize + ReLU apply (h0 path), wide, hi-occ ---
// grid (H0N/64, 64); block 256. Each block: reduce 32 partials for 64 cols,
// then apply BN+ReLU to a 64x64 tile with uint4 (8-half) loads/stores.
__global__ void __launch_bounds__(256)
bnfin_relu_kernel(const float* __restrict__ ps, const float* __restrict__ psq,
                  const float* __restrict__ g, const float* __restrict__ be,
                  const __half* __restrict__ H, __half* __restrict__ Ht) {
    __shared__ float red_s[4][64], red_q[4][64];
    __shared__ float sc_s[64], sc_h[64];
    int t = threadIdx.x;
    int c64 = t & 63, grp = t >> 6;                // 4 groups of 8 chunks
    int col = blockIdx.x * 64 + c64;
    float s = 0.f, q = 0.f;
    #pragma unroll
    for (int i = 0; i < 8; i++) {
        long o = (long)(grp * 8 + i) * H0N + col;
        s += ps[o]; q += psq[o];
    }
    red_s[grp][c64] = s; red_q[grp][c64] = q;
    __syncthreads();
    if (grp == 0) {
        #pragma unroll
        for (int i = 1; i < 4; i++) { s += red_s[i][c64]; q += red_q[i][c64]; }
        float mean = s * (1.f / BB);
        float var  = q * (1.f / BB) - mean * mean;
        float sc   = g[col] * rsqrtf(var + EPSV);
        sc_s[c64] = sc;
        sc_h[c64] = be[col] - mean * sc;
    }
    __syncthreads();
    // apply: 8 cols per thread (uint4); 32 rows per iter; 2 iters for 64 rows.
    int c8 = (t & 7) * 8;
    int rw = t >> 3;                               // 0..31
    float scv[8], shv[8];
    #pragma unroll
    for (int j = 0; j < 8; j++) { scv[j] = sc_s[c8 + j]; shv[j] = sc_h[c8 + j]; }
    #pragma unroll
    for (int it = 0; it < 2; it++) {
        int row = blockIdx.y * 64 + it * 32 + rw;
        long idx = (long)row * H0N + blockIdx.x * 64 + c8;
        uint4 raw = *(const uint4*)&H[idx];
        const __half2* hp = (const __half2*)&raw;
        uint4 ow;
        __half2* op = (__half2*)&ow;
        #pragma unroll
        for (int j = 0; j < 4; j++) {
            float2 v = __half22float2(hp[j]);
            float a = fmaxf(0.f, v.x * scv[2 * j] + shv[2 * j]);
            float b = fmaxf(0.f, v.y * scv[2 * j + 1] + shv[2 * j + 1]);
            op[j] = __floats2half2_rn(a, b);
        }
        *(uint4*)&Ht[idx] = ow;
    }
}

// ---------------- fused BN1 finalize + final dot + sigmoid, wide -----------
// grid 64; block 256 (8 warps x 8 rows each). Phase 1: all 512 scale/shift
// + w2 staged into smem. Phase 2: uint4 dot + sigmoid.
__global__ void __launch_bounds__(256)
final_kernel(const float* __restrict__ ps, const float* __restrict__ psq,
             const float* __restrict__ g, const float* __restrict__ be,
             const __half* __restrict__ H1,
             const float* __restrict__ w2, const float* __restrict__ b2,
             const float* __restrict__ lin, const float* __restrict__ bias0,
             float* __restrict__ out) {
    __shared__ float sc_s[H1N], sc_h[H1N], sm_w2[H1N];
    int t = threadIdx.x;
    #pragma unroll
    for (int h = 0; h < 2; h++) {
        int col = t + h * 256;
        float s = 0.f, q = 0.f;
        #pragma unroll
        for (int i = 0; i < RCH; i++) {
            long o = (long)i * H1N + col;
            s += ps[o]; q += psq[o];
        }
        float mean = s * (1.f / BB);
        float var  = q * (1.f / BB) - mean * mean;
        float sc   = g[col] * rsqrtf(var + EPSV);
        sc_s[col] = sc;
        sc_h[col] = be[col] - mean * sc;
        sm_w2[col] = w2[col];
    }
    __syncthreads();

    int warp = t >> 5, lane = t & 31;
    #pragma unroll
    for (int rr = 0; rr < 8; rr++) {
        int row = blockIdx.x * 64 + warp * 8 + rr;
        float acc = 0.f;
        #pragma unroll
        for (int it = 0; it < 2; it++) {
            int k = (lane + it * 32) * 8;
            uint4 raw = *(const uint4*)&H1[(long)row * H1N + k];
            const __half2* hp = (const __half2*)&raw;
            #pragma unroll
            for (int j = 0; j < 4; j++) {
                float2 v = __half22float2(hp[j]);
                int kk = k + 2 * j;
                float a = fmaxf(0.f, v.x * sc_s[kk] + sc_h[kk]);
                float b = fmaxf(0.f, v.y * sc_s[kk + 1] + sc_h[kk + 1]);
                acc += a * sm_w2[kk] + b * sm_w2[kk + 1];
            }
        }
        #pragma unroll
        for (int o = 16; o > 0; o >>= 1) acc += __shfl_xor_sync(0xffffffffu, acc, o);
        if (lane == 0) {
            float logit = acc + b2[0] + lin[row] + bias0[0];
            out[row] = 1.f / (1.f + expf(-logit));
        }
    }
}

// ---------------------------------------------------------------------------
extern "C" void kernel_launch(void* const* d_in, const int* in_sizes, int n_in,
                              void* d_out, int out_size) {
    const int*   x    = (const int*)d_in[0];
    const float* emb  = (const float*)d_in[1];
    const float* lint = (const float*)d_in[2];
    const float* bias = (const float*)d_in[3];
    const float* sw1  = (const float*)d_in[4];
    const float* sw2  = (const float*)d_in[5];
    const float* bilW = (const float*)d_in[6];
    const float* w0   = (const float*)d_in[7];
    const float* b0   = (const float*)d_in[8];
    const float* g0   = (const float*)d_in[9];
    const float* be0  = (const float*)d_in[10];
    const float* w1   = (const float*)d_in[11];
    const float* b1   = (const float*)d_in[12];
    const float* g1   = (const float*)d_in[13];
    const float* be1  = (const float*)d_in[14];
    const float* w2   = (const float*)d_in[15];
    const float* b2   = (const float*)d_in[16];
    float* out = (float*)d_out;

    __half *E2h, *WTn, *comb, *h0h, *h0t, *h1h, *w0t, *w1t;
    float *lin, *ps, *psq;
    cudaGetSymbolAddress((void**)&E2h,  g_E2h);
    cudaGetSymbolAddress((void**)&WTn,  g_WTn);
    cudaGetSymbolAddress((void**)&comb, g_comb);
    cudaGetSymbolAddress((void**)&h0h,  g_h0h);
    cudaGetSymbolAddress((void**)&h0t,  g_h0t);
    cudaGetSymbolAddress((void**)&h1h,  g_h1h);
    cudaGetSymbolAddress((void**)&w0t,  g_w0t);
    cudaGetSymbolAddress((void**)&w1t,  g_w1t);
    cudaGetSymbolAddress((void**)&lin,  g_lin);
    cudaGetSymbolAddress((void**)&ps,   g_ps);
    cudaGetSymbolAddress((void**)&psq,  g_psq);

    // P: all independent producers in one launch (gather blocks first)
    prep_kernel<<<GB_TOTAL, 256>>>(x, emb, lint, sw1, sw2, bilW, w0, w1,
                                   E2h, WTn, w0t, w1t, lin);
    // G1: comb = (E2 @ WTn^T) * E2 -> [p|q] scatter (fp16)
    hgemm_kernel<false, true, false><<<dim3(2 * BB / 128, FD / 128), 128>>>(
        E2h, WTn, comb, 2 * BB, FD, FD, nullptr, E2h, nullptr, nullptr);
    // G2: h0 = comb @ w0 + b0 (fp16) + fused BN partials
    hgemm_kernel<true, false, true><<<dim3(BB / 128, H0N / 128), 128>>>(
        comb, w0t, h0h, BB, H0N, COMB, b0, nullptr, ps, psq);
    // fused BN0 finalize + ReLU apply (wide, high-occupancy)
    bnfin_relu_kernel<<<dim3(H0N / 64, 64), 256>>>(ps, psq, g0, be0, h0h, h0t);
    // G3: h1 = h0t @ w1 + b1 (fp16) + fused BN partials
    hgemm_kernel<true, false, true><<<dim3(BB / 128, H1N / 128), 128>>>(
        h0t, w1t, h1h, BB, H1N, H0N, b1, nullptr, ps, psq);
    // fused BN1 finalize + final dot + sigmoid (wide)
    final_kernel<<<BB / 64, 256>>>(ps, psq, g1, be1, h1h, w2, b2, lin, bias, out);
}